// round 5
// baseline (speedup 1.0000x reference)
#include <cuda_runtime.h>
#include <math.h>

#define N_DRUG   8000
#define N_DIS    20000
#define DDIM     128
#define E_DD     2048
#define E_NN     1000000
#define JSPLIT   18
#define NJT      157            /* ceil(20000/128) j-tiles of 128 */
#define NDIS_PAD 20096          /* 157*128, padded cols of transposed matrix */

/* ---------------- device scratch (no allocations allowed) ---------------- */
__device__ float g_inv_norm[N_DIS];
__device__ float g_nd [N_DIS * DDIM];       /* normalized h_disease, row-major */
__device__ float g_ndT[DDIM * NDIS_PAD];    /* normalized, transposed [k][j];
                                               pad cols stay 0 (zero-init)    */
__device__ float g_cand_val[E_DD * JSPLIT * 3];
__device__ int   g_cand_idx[E_DD * JSPLIT * 3];

/* ---------------- top-3 insert (desc value; ties keep earlier) ----------- */
__device__ __forceinline__ void ins3(float v, int id,
                                     float &v0, int &i0,
                                     float &v1, int &i1,
                                     float &v2, int &i2) {
    if (v > v0)      { v2 = v1; i2 = i1; v1 = v0; i1 = i0; v0 = v; i0 = id; }
    else if (v > v1) { v2 = v1; i2 = i1; v1 = v;  i1 = id; }
    else if (v > v2) { v2 = v;  i2 = id; }
}

/* ---------------- packed f32x2 FMA (FFMA2 — ptxas never emits this) ------ */
__device__ __forceinline__ void ffma2(unsigned long long &acc,
                                      unsigned long long a,
                                      unsigned long long b) {
    asm volatile("fma.rn.f32x2 %0, %1, %2, %0;" : "+l"(acc) : "l"(a), "l"(b));
}
__device__ __forceinline__ unsigned long long pack2(float x) {
    unsigned long long r;
    asm("mov.b64 %0, {%1, %1};" : "=l"(r) : "f"(x));
    return r;
}

/* ================= kernel 1a: per-row 1/(||x||+eps) ====================== */
__global__ void k_inv_norm(const float* __restrict__ hd) {
    int w    = (blockIdx.x * blockDim.x + threadIdx.x) >> 5;
    int lane = threadIdx.x & 31;
    if (w >= N_DIS) return;
    float4 v = ((const float4*)hd)[w * 32 + lane];
    float ss = v.x*v.x + v.y*v.y + v.z*v.z + v.w*v.w;
    #pragma unroll
    for (int o = 16; o; o >>= 1) ss += __shfl_xor_sync(0xffffffffu, ss, o);
    if (lane == 0) g_inv_norm[w] = 1.0f / (sqrtf(ss) + 1e-8f);
}

/* ====== kernel 1b: write normalized row-major AND transposed copies ====== */
__global__ void k_norm_transpose(const float* __restrict__ hd) {
    __shared__ float s[32][132];
    int i0 = blockIdx.x * 32;
    int t  = threadIdx.x;
    for (int idx = t; idx < 32 * 32; idx += 256) {
        int r = idx >> 5, c = idx & 31;
        float  sc = g_inv_norm[i0 + r];
        float4 v  = ((const float4*)hd)[(i0 + r) * 32 + c];
        v.x *= sc; v.y *= sc; v.z *= sc; v.w *= sc;
        ((float4*)g_nd)[(i0 + r) * 32 + c] = v;
        s[r][c*4+0] = v.x; s[r][c*4+1] = v.y; s[r][c*4+2] = v.z; s[r][c*4+3] = v.w;
    }
    __syncthreads();
    for (int idx = t; idx < 128 * 8; idx += 256) {
        int k = idx >> 3, c4 = idx & 7;
        int ii = c4 * 4;
        float4 v = make_float4(s[ii][k], s[ii+1][k], s[ii+2][k], s[ii+3][k]);
        ((float4*)g_ndT)[k * (NDIS_PAD/4) + (i0 >> 2) + c4] = v;
    }
}

/* ======= kernel 2: FFMA2 sim-GEMM (128x128 tile, 8x8/thread) + top-3 ===== */
#define SMEM_AT_F  (128 * 128)     /* A transposed [k][e]         = 64 KB */
#define SMEM_B_F   (64 * 128)      /* B chunk      [k][j]         = 32 KB */
#define SMEM_BYTES ((SMEM_AT_F + SMEM_B_F + 128*3) * 4 + 128*3*4 + 128*4)

__global__ void __launch_bounds__(256, 2) k_gemm_topk(const int* __restrict__ dst_dd) {
    extern __shared__ float sm[];
    float* At    = sm;                       /* [128 k][128 e]            */
    float* Bs    = At + SMEM_AT_F;           /* [64 k][128 j]             */
    float* run_v = Bs + SMEM_B_F;            /* [128][3] running top3     */
    int*   run_i = (int*)(run_v + 128 * 3);
    int*   sdst  = run_i + 128 * 3;          /* [128]                     */

    const int t  = threadIdx.x;
    const int tx = t & 15, ty = t >> 4;
    const int e0 = blockIdx.x * 128;
    const int myRows = ty * 8;

    if (t < 128) {
        sdst[t] = dst_dd[e0 + t];
        run_v[t*3+0] = -1e30f; run_v[t*3+1] = -1e30f; run_v[t*3+2] = -1e30f;
        run_i[t*3+0] = -1;     run_i[t*3+1] = -1;     run_i[t*3+2] = -1;
    }
    __syncthreads();
    /* load A transposed; warp writes 32 consecutive e at fixed k -> conflict-free STS */
    for (int idx = t; idx < 128 * 32; idx += 256) {
        int r = idx & 127, c4 = idx >> 7;
        float4 v = ((const float4*)g_nd)[sdst[r] * 32 + c4];
        At[(c4*4 + 0) * 128 + r] = v.x;
        At[(c4*4 + 1) * 128 + r] = v.y;
        At[(c4*4 + 2) * 128 + r] = v.z;
        At[(c4*4 + 3) * 128 + r] = v.w;
    }
    /* (first B-load __syncthreads below also fences the At writes) */

    for (int jt = blockIdx.y; jt < NJT; jt += JSPLIT) {
        const int j0 = jt * 128;
        unsigned long long acc[8][4];
        #pragma unroll
        for (int e = 0; e < 8; e++)
            #pragma unroll
            for (int p = 0; p < 4; p++) acc[e][p] = 0ull;

        #pragma unroll
        for (int c = 0; c < 2; c++) {
            __syncthreads();                 /* Bs free to overwrite */
            for (int idx = t; idx < 64 * 32; idx += 256) {
                int r = idx >> 5, q = idx & 31;
                ((float4*)Bs)[r * 32 + q] =
                    ((const float4*)g_ndT)[(c*64 + r) * (NDIS_PAD/4) + (j0 >> 2) + q];
            }
            __syncthreads();

            #pragma unroll 4
            for (int k = 0; k < 64; k++) {
                const float* ak = At + (c*64 + k) * 128 + myRows;
                float4 alo = *(const float4*)(ak);
                float4 ahi = *(const float4*)(ak + 4);
                ulonglong2 bA = *(const ulonglong2*)(Bs + k*128 + tx*8);
                ulonglong2 bB = *(const ulonglong2*)(Bs + k*128 + tx*8 + 4);
                #define MM_ROW(E, AS) {                                   \
                    unsigned long long a2 = pack2(AS);                    \
                    ffma2(acc[E][0], a2, bA.x);                           \
                    ffma2(acc[E][1], a2, bA.y);                           \
                    ffma2(acc[E][2], a2, bB.x);                           \
                    ffma2(acc[E][3], a2, bB.y); }
                MM_ROW(0, alo.x) MM_ROW(1, alo.y) MM_ROW(2, alo.z) MM_ROW(3, alo.w)
                MM_ROW(4, ahi.x) MM_ROW(5, ahi.y) MM_ROW(6, ahi.z) MM_ROW(7, ahi.w)
                #undef MM_ROW
            }
        }

        /* top-3 from registers: local over 8 j, then width-16 shfl tree    */
        #pragma unroll
        for (int e = 0; e < 8; e++) {
            int row   = myRows + e;
            int myDst = sdst[row];
            float v0 = -1e30f, v1 = -1e30f, v2 = -1e30f;
            int   a0 = -1, a1 = -1, a2i = -1;
            #pragma unroll
            for (int p = 0; p < 4; p++) {
                unsigned long long v = acc[e][p];
                float lo = __uint_as_float((unsigned)v);
                float hi = __uint_as_float((unsigned)(v >> 32));
                int jg = j0 + tx*8 + p*2;
                if (jg     < N_DIS && jg     != myDst) ins3(lo, jg,   v0,a0,v1,a1,v2,a2i);
                if (jg + 1 < N_DIS && jg + 1 != myDst) ins3(hi, jg+1, v0,a0,v1,a1,v2,a2i);
            }
            #pragma unroll
            for (int off = 8; off; off >>= 1) {
                float w0 = __shfl_down_sync(0xffffffffu, v0,  off, 16);
                float w1 = __shfl_down_sync(0xffffffffu, v1,  off, 16);
                float w2 = __shfl_down_sync(0xffffffffu, v2,  off, 16);
                int   b0 = __shfl_down_sync(0xffffffffu, a0,  off, 16);
                int   b1 = __shfl_down_sync(0xffffffffu, a1,  off, 16);
                int   b2 = __shfl_down_sync(0xffffffffu, a2i, off, 16);
                if (b0 >= 0) ins3(w0, b0, v0,a0,v1,a1,v2,a2i);
                if (b1 >= 0) ins3(w1, b1, v0,a0,v1,a1,v2,a2i);
                if (b2 >= 0) ins3(w2, b2, v0,a0,v1,a1,v2,a2i);
            }
            if (tx == 0) {                   /* single writer per row */
                float r0 = run_v[row*3+0], r1 = run_v[row*3+1], r2 = run_v[row*3+2];
                int   q0 = run_i[row*3+0], q1 = run_i[row*3+1], q2 = run_i[row*3+2];
                if (a0  >= 0) ins3(v0, a0,  r0,q0,r1,q1,r2,q2);
                if (a1  >= 0) ins3(v1, a1,  r0,q0,r1,q1,r2,q2);
                if (a2i >= 0) ins3(v2, a2i, r0,q0,r1,q1,r2,q2);
                run_v[row*3+0] = r0; run_v[row*3+1] = r1; run_v[row*3+2] = r2;
                run_i[row*3+0] = q0; run_i[row*3+1] = q1; run_i[row*3+2] = q2;
            }
        }
    }
    __syncthreads();
    if (t < 128) {
        int base = ((e0 + t) * JSPLIT + blockIdx.y) * 3;
        g_cand_val[base+0] = run_v[t*3+0]; g_cand_idx[base+0] = run_i[t*3+0];
        g_cand_val[base+1] = run_v[t*3+1]; g_cand_idx[base+1] = run_i[t*3+1];
        g_cand_val[base+2] = run_v[t*3+2]; g_cand_idx[base+2] = run_i[t*3+2];
    }
}

/* ==== kernel 3: merge candidates, softmax, prototype, score_dd =========== */
__global__ void k_score_dd(const float* __restrict__ h_drug,
                           const float* __restrict__ h_dis,
                           const float* __restrict__ W,
                           const int*   __restrict__ src_dd,
                           const int*   __restrict__ dst_dd,
                           const int*   __restrict__ deg,
                           float*       __restrict__ out) {
    int e    = (blockIdx.x * blockDim.x + threadIdx.x) >> 5;
    int lane = threadIdx.x & 31;
    if (e >= E_DD) return;

    float w0 = 0.f, w1 = 0.f, w2 = 0.f;
    int   i0 = 0, i1 = 0, i2 = 0;
    if (lane == 0) {
        float v0 = -1e30f, v1 = -1e30f, v2 = -1e30f;
        int   a0 = -1, a1 = -1, a2 = -1;
        #pragma unroll 6
        for (int c = 0; c < JSPLIT * 3; c++) {
            float v  = g_cand_val[e * JSPLIT * 3 + c];
            int   id = g_cand_idx[e * JSPLIT * 3 + c];
            if (id >= 0) ins3(v, id, v0, a0, v1, a1, v2, a2);
        }
        float x1 = expf(v1 - v0), x2 = expf(v2 - v0);
        float s  = 1.f + x1 + x2;
        w0 = 1.f / s; w1 = x1 / s; w2 = x2 / s;
        i0 = a0; i1 = a1; i2 = a2;
    }
    w0 = __shfl_sync(0xffffffffu, w0, 0);
    w1 = __shfl_sync(0xffffffffu, w1, 0);
    w2 = __shfl_sync(0xffffffffu, w2, 0);
    i0 = __shfl_sync(0xffffffffu, i0, 0);
    i1 = __shfl_sync(0xffffffffu, i1, 0);
    i2 = __shfl_sync(0xffffffffu, i2, 0);

    int   sidx = src_dd[e], didx = dst_dd[e];
    float coef = expf(-0.7f * (float)deg[didx]);
    float om   = 1.f - coef;

    float4 sv = ((const float4*)h_drug)[sidx * 32 + lane];
    float4 wv = ((const float4*)W)[lane];            /* W row 0 */
    float4 dv = ((const float4*)h_dis)[didx * 32 + lane];
    float4 p0 = ((const float4*)h_dis)[i0 * 32 + lane];
    float4 p1 = ((const float4*)h_dis)[i1 * 32 + lane];
    float4 p2 = ((const float4*)h_dis)[i2 * 32 + lane];

    float r =
        sv.x * wv.x * (om * dv.x + coef * (w0*p0.x + w1*p1.x + w2*p2.x)) +
        sv.y * wv.y * (om * dv.y + coef * (w0*p0.y + w1*p1.y + w2*p2.y)) +
        sv.z * wv.z * (om * dv.z + coef * (w0*p0.z + w1*p1.z + w2*p2.z)) +
        sv.w * wv.w * (om * dv.w + coef * (w0*p0.w + w1*p1.w + w2*p2.w));
    #pragma unroll
    for (int o = 16; o; o >>= 1) r += __shfl_xor_sync(0xffffffffu, r, o);
    if (lane == 0) out[e] = r;
}

/* ==== kernel 4: score_nn — warp per edge, L2-resident gather-dot ========= */
__global__ void k_score_nn(const float* __restrict__ h_dis,
                           const float* __restrict__ W,
                           const int*   __restrict__ src,
                           const int*   __restrict__ dst,
                           float*       __restrict__ out) {
    int e    = (int)((blockIdx.x * (unsigned)blockDim.x + threadIdx.x) >> 5);
    int lane = threadIdx.x & 31;
    if (e >= E_NN) return;
    int s = __ldg(src + e), d = __ldg(dst + e);
    float4 a = ((const float4*)h_dis)[s * 32 + lane];
    float4 b = ((const float4*)h_dis)[d * 32 + lane];
    float4 w = ((const float4*)W)[32 + lane];        /* W row 1 */
    float r = a.x*w.x*b.x + a.y*w.y*b.y + a.z*w.z*b.z + a.w*w.w*b.w;
    #pragma unroll
    for (int o = 16; o; o >>= 1) r += __shfl_xor_sync(0xffffffffu, r, o);
    if (lane == 0) out[E_DD + e] = r;
}

/* ========================================================================= */
extern "C" void kernel_launch(void* const* d_in, const int* in_sizes, int n_in,
                              void* d_out, int out_size) {
    const float* h_drug = (const float*)d_in[0];
    const float* h_dis  = (const float*)d_in[1];
    const float* W      = (const float*)d_in[2];
    const int*   src_dd = (const int*)d_in[3];
    const int*   dst_dd = (const int*)d_in[4];
    const int*   src_nn = (const int*)d_in[5];
    const int*   dst_nn = (const int*)d_in[6];
    const int*   deg    = (const int*)d_in[7];
    float* out = (float*)d_out;

    (void)cudaFuncSetAttribute(k_gemm_topk,
                               cudaFuncAttributeMaxDynamicSharedMemorySize,
                               SMEM_BYTES);

    /* big memory-bound kernel first */
    k_score_nn<<<(E_NN * 32 + 255) / 256, 256>>>(h_dis, W, src_nn, dst_nn, out);

    k_inv_norm<<<(N_DIS * 32 + 255) / 256, 256>>>(h_dis);
    k_norm_transpose<<<N_DIS / 32, 256>>>(h_dis);
    k_gemm_topk<<<dim3(E_DD / 128, JSPLIT), 256, SMEM_BYTES>>>(dst_dd);
    k_score_dd<<<(E_DD * 32 + 255) / 256, 256>>>(h_drug, h_dis, W,
                                                 src_dd, dst_dd, deg, out);
}

// round 11
// speedup vs baseline: 1.6064x; 1.6064x over previous
#include <cuda_runtime.h>
#include <cuda_bf16.h>
#include <stdint.h>
#include <math.h>

#define N_DIS   20000
#define DDIM    128
#define E_DD    2048
#define E_NN    1000000
#define NSPLIT  9
#define NJT     157              /* ceil(20000/128) j-tiles of 128 */
#define NDP     20096            /* 157*128 padded disease rows */

#define ROW_W   68               /* padded smem words per B row (272 B) */
#define BUF_B   (128 * ROW_W * 4)/* 34816 bytes per B buffer */
#define BUF_W   (128 * ROW_W)    /* words per buffer */
#define SMEM_TOT (2 * BUF_B)     /* 69632 */

/* ---------------- device scratch (zero-init; no allocs allowed) ---------- */
__device__ float g_inv_norm[N_DIS];
__device__ float g_nd[N_DIS * DDIM];     /* normalized fp32, row-major        */
__device__ uint4 g_ndb4[NDP * 16];       /* normalized bf16; pad rows stay 0  */
__device__ uint4 g_qb4[E_DD * 16];       /* query rows (dst gather) bf16      */
__device__ float g_cv[E_DD * NSPLIT * 4];
__device__ int   g_ci[E_DD * NSPLIT * 4];

/* ---------------- helpers ------------------------------------------------ */
__device__ __forceinline__ uint32_t smem_u32(const void* p) {
    uint32_t a;
    asm("{ .reg .u64 t; cvta.to.shared.u64 t, %1; cvt.u32.u64 %0, t; }"
        : "=r"(a) : "l"(p));
    return a;
}
__device__ __forceinline__ unsigned bf2(float a, float b) {
    unsigned r;
    asm("{ .reg .b16 lo, hi; cvt.rn.bf16.f32 lo, %1; cvt.rn.bf16.f32 hi, %2;"
        " mov.b32 %0, {lo, hi}; }" : "=r"(r) : "f"(a), "f"(b));
    return r;
}
__device__ __forceinline__ void cpa16(uint32_t saddr, const void* g) {
    asm volatile("cp.async.cg.shared.global [%0], [%1], 16;"
                 :: "r"(saddr), "l"(g) : "memory");
}
#define CP_COMMIT() asm volatile("cp.async.commit_group;" ::: "memory")
#define CP_WAIT(n)  asm volatile("cp.async.wait_group %0;" :: "n"(n) : "memory")

__device__ __forceinline__ void mma16816(float* c, const uint32_t* a,
                                         uint32_t b0, uint32_t b1) {
    asm volatile(
        "mma.sync.aligned.m16n8k16.row.col.f32.bf16.bf16.f32 "
        "{%0,%1,%2,%3}, {%4,%5,%6,%7}, {%8,%9}, {%0,%1,%2,%3};"
        : "+f"(c[0]), "+f"(c[1]), "+f"(c[2]), "+f"(c[3])
        : "r"(a[0]), "r"(a[1]), "r"(a[2]), "r"(a[3]), "r"(b0), "r"(b1));
}

/* top-4 insert (desc; earlier wins ties) */
__device__ __forceinline__ void ins4(float v, int id,
                                     float &v0, int &i0, float &v1, int &i1,
                                     float &v2, int &i2, float &v3, int &i3) {
    if (v > v0)      { v3=v2;i3=i2; v2=v1;i2=i1; v1=v0;i1=i0; v0=v;i0=id; }
    else if (v > v1) { v3=v2;i3=i2; v2=v1;i2=i1; v1=v;i1=id; }
    else if (v > v2) { v3=v2;i3=i2; v2=v;i2=id; }
    else if (v > v3) { v3=v;i3=id; }
}
/* top-3 insert */
__device__ __forceinline__ void ins3(float v, int id,
                                     float &v0, int &i0, float &v1, int &i1,
                                     float &v2, int &i2) {
    if (v > v0)      { v2 = v1; i2 = i1; v1 = v0; i1 = i0; v0 = v; i0 = id; }
    else if (v > v1) { v2 = v1; i2 = i1; v1 = v;  i1 = id; }
    else if (v > v2) { v2 = v;  i2 = id; }
}

/* ================= kernel 1a: per-row 1/(||x||+eps) ====================== */
__global__ void k_inv_norm(const float* __restrict__ hd) {
    int w    = (blockIdx.x * blockDim.x + threadIdx.x) >> 5;
    int lane = threadIdx.x & 31;
    if (w >= N_DIS) return;
    float4 v = ((const float4*)hd)[w * 32 + lane];
    float ss = v.x*v.x + v.y*v.y + v.z*v.z + v.w*v.w;
    #pragma unroll
    for (int o = 16; o; o >>= 1) ss += __shfl_xor_sync(0xffffffffu, ss, o);
    if (lane == 0) g_inv_norm[w] = 1.0f / (sqrtf(ss) + 1e-8f);
}

/* ====== kernel 1b: normalized fp32 + bf16 copies ========================= */
__global__ void k_prep(const float* __restrict__ hd) {
    int gid = blockIdx.x * blockDim.x + threadIdx.x;
    if (gid >= N_DIS * 16) return;
    int row = gid >> 4, h = gid & 15;
    float sc = g_inv_norm[row];
    float4 a = ((const float4*)hd)[row * 32 + h * 2];
    float4 b = ((const float4*)hd)[row * 32 + h * 2 + 1];
    a.x *= sc; a.y *= sc; a.z *= sc; a.w *= sc;
    b.x *= sc; b.y *= sc; b.z *= sc; b.w *= sc;
    ((float4*)g_nd)[row * 32 + h * 2]     = a;
    ((float4*)g_nd)[row * 32 + h * 2 + 1] = b;
    uint4 o;
    o.x = bf2(a.x, a.y); o.y = bf2(a.z, a.w);
    o.z = bf2(b.x, b.y); o.w = bf2(b.z, b.w);
    g_ndb4[row * 16 + h] = o;
}

/* ====== kernel 1c: gather query rows (bf16) ============================== */
__global__ void k_pack_q(const int* __restrict__ dst_dd) {
    int gid = blockIdx.x * blockDim.x + threadIdx.x;
    if (gid >= E_DD * 16) return;
    int e = gid >> 4, h = gid & 15;
    int d = dst_dd[e];
    float4 a = ((const float4*)g_nd)[d * 32 + h * 2];
    float4 b = ((const float4*)g_nd)[d * 32 + h * 2 + 1];
    uint4 o;
    o.x = bf2(a.x, a.y); o.y = bf2(a.z, a.w);
    o.z = bf2(b.x, b.y); o.w = bf2(b.z, b.w);
    g_qb4[e * 16 + h] = o;
}

/* ======= kernel 2: mma.sync bf16 sim-GEMM + fused approx top-4 =========== */
/* grid (16, NSPLIT), 256 threads = 8 warps; warp w owns rows m0+16w..+15.  */
__global__ void __launch_bounds__(256) k_simtopk(const int* __restrict__ dst_dd) {
    extern __shared__ uint32_t smw[];
    const uint32_t sb = smem_u32(smw);
    const int t = threadIdx.x, lane = t & 31, warp = t >> 5;
    const int tc = lane & 3, gr = lane >> 2;            /* thread col / group row */
    const int m0 = blockIdx.x * 128;
    const int jt0 = blockIdx.y;
    const int nch = 1 + (NJT - 1 - jt0) / NSPLIT;

    const uint32_t* qw = (const uint32_t*)g_qb4;

    /* A fragments for this warp's 16 rows, all 8 k-steps: loaded once.     */
    const int rA = m0 + warp * 16 + gr;                 /* global edge row  */
    uint32_t af[8][4];
    #pragma unroll
    for (int ks = 0; ks < 8; ks++) {
        af[ks][0] = qw[rA       * 64 + ks * 8 + tc];
        af[ks][1] = qw[(rA + 8) * 64 + ks * 8 + tc];
        af[ks][2] = qw[rA       * 64 + ks * 8 + tc + 4];
        af[ks][3] = qw[(rA + 8) * 64 + ks * 8 + tc + 4];
    }
    const int dstA = dst_dd[rA];
    const int dstB = dst_dd[rA + 8];

    /* running top-4 for rows rA (sel 0) and rA+8 (sel 1) — valid on tc==0 */
    float rv[2][4]; int ri[2][4];
    #pragma unroll
    for (int s = 0; s < 2; s++)
        #pragma unroll
        for (int k = 0; k < 4; k++) { rv[s][k] = -1e30f; ri[s][k] = -1; }

    /* prefetch chunk 0 */
    {
        int j0r = jt0 * 128;
        for (int idx = t; idx < 2048; idx += 256) {
            int r = idx >> 4, c = idx & 15;
            cpa16(sb + r * (ROW_W * 4) + c * 16, &g_ndb4[(j0r + r) * 16 + c]);
        }
        CP_COMMIT();
    }

    for (int i = 0; i < nch; i++) {
        if (i + 1 < nch) {                 /* prefetch chunk i+1 into buf (i+1)&1 */
            int jn = (jt0 + (i + 1) * NSPLIT) * 128;
            uint32_t bb = sb + ((i + 1) & 1) * BUF_B;
            for (int idx = t; idx < 2048; idx += 256) {
                int r = idx >> 4, c = idx & 15;
                cpa16(bb + r * (ROW_W * 4) + c * 16, &g_ndb4[(jn + r) * 16 + c]);
            }
            CP_COMMIT();
            CP_WAIT(1);                    /* chunk i complete */
        } else {
            CP_WAIT(0);
        }
        __syncthreads();                   /* buf i&1 visible to all warps  */

        float acc[16][4];
        #pragma unroll
        for (int nt = 0; nt < 16; nt++)
            #pragma unroll
            for (int k = 0; k < 4; k++) acc[nt][k] = 0.f;

        const uint32_t* bw = smw + (i & 1) * BUF_W;
        #pragma unroll
        for (int ks = 0; ks < 8; ks++) {
            #pragma unroll
            for (int nt = 0; nt < 16; nt++) {
                int wbase = (nt * 8 + gr) * ROW_W + ks * 8 + tc;
                uint32_t b0 = bw[wbase];
                uint32_t b1 = bw[wbase + 4];
                mma16816(acc[nt], af[ks], b0, b1);
            }
        }
        __syncthreads();                   /* done reading buf i&1          */

        /* fused per-chunk top-4: thread owns rows rA (c0,c1) & rA+8 (c2,c3) */
        int j0 = (jt0 + i * NSPLIT) * 128;
        #pragma unroll
        for (int sel = 0; sel < 2; sel++) {
            int dst = sel ? dstB : dstA;
            float v0 = -1e30f, v1 = -1e30f, v2 = -1e30f, v3 = -1e30f;
            int   a0 = -1, a1 = -1, a2 = -1, a3 = -1;
            #pragma unroll
            for (int nt = 0; nt < 16; nt++) {
                int j = j0 + nt * 8 + tc * 2;
                float x0 = acc[nt][sel * 2 + 0];
                float x1 = acc[nt][sel * 2 + 1];
                if (j     < N_DIS && j     != dst) ins4(x0, j,   v0,a0,v1,a1,v2,a2,v3,a3);
                if (j + 1 < N_DIS && j + 1 != dst) ins4(x1, j+1, v0,a0,v1,a1,v2,a2,v3,a3);
            }
            /* merge across the 4 lanes sharing this row */
            #pragma unroll
            for (int off = 1; off <= 2; off <<= 1) {
                float w0 = __shfl_xor_sync(0xffffffffu, v0, off);
                float w1 = __shfl_xor_sync(0xffffffffu, v1, off);
                float w2 = __shfl_xor_sync(0xffffffffu, v2, off);
                float w3 = __shfl_xor_sync(0xffffffffu, v3, off);
                int   b0 = __shfl_xor_sync(0xffffffffu, a0, off);
                int   b1 = __shfl_xor_sync(0xffffffffu, a1, off);
                int   b2 = __shfl_xor_sync(0xffffffffu, a2, off);
                int   b3 = __shfl_xor_sync(0xffffffffu, a3, off);
                if (b0 >= 0) ins4(w0, b0, v0,a0,v1,a1,v2,a2,v3,a3);
                if (b1 >= 0) ins4(w1, b1, v0,a0,v1,a1,v2,a2,v3,a3);
                if (b2 >= 0) ins4(w2, b2, v0,a0,v1,a1,v2,a2,v3,a3);
                if (b3 >= 0) ins4(w3, b3, v0,a0,v1,a1,v2,a2,v3,a3);
            }
            /* fold into running top-4 */
            if (a0 >= 0) ins4(v0, a0, rv[sel][0],ri[sel][0], rv[sel][1],ri[sel][1],
                                       rv[sel][2],ri[sel][2], rv[sel][3],ri[sel][3]);
            if (a1 >= 0) ins4(v1, a1, rv[sel][0],ri[sel][0], rv[sel][1],ri[sel][1],
                                       rv[sel][2],ri[sel][2], rv[sel][3],ri[sel][3]);
            if (a2 >= 0) ins4(v2, a2, rv[sel][0],ri[sel][0], rv[sel][1],ri[sel][1],
                                       rv[sel][2],ri[sel][2], rv[sel][3],ri[sel][3]);
            if (a3 >= 0) ins4(v3, a3, rv[sel][0],ri[sel][0], rv[sel][1],ri[sel][1],
                                       rv[sel][2],ri[sel][2], rv[sel][3],ri[sel][3]);
        }
    }

    if (tc == 0) {
        #pragma unroll
        for (int sel = 0; sel < 2; sel++) {
            int row = rA + sel * 8;
            int base = (row * NSPLIT + jt0) * 4;
            g_cv[base+0] = rv[sel][0]; g_ci[base+0] = ri[sel][0];
            g_cv[base+1] = rv[sel][1]; g_ci[base+1] = ri[sel][1];
            g_cv[base+2] = rv[sel][2]; g_ci[base+2] = ri[sel][2];
            g_cv[base+3] = rv[sel][3]; g_ci[base+3] = ri[sel][3];
        }
    }
}

/* ---------------- top-6 insert (lane-0 merge) ---------------------------- */
__device__ __forceinline__ void ins6(float v, int id,
    float &a0,int &b0, float &a1,int &b1, float &a2,int &b2,
    float &a3,int &b3, float &a4,int &b4, float &a5,int &b5) {
    if (v <= a5) return;
    a5 = v; b5 = id;
    if (a5 > a4) { float tv=a4; int ti=b4; a4=a5; b4=b5; a5=tv; b5=ti;
      if (a4 > a3) { tv=a3; ti=b3; a3=a4; b3=b4; a4=tv; b4=ti;
        if (a3 > a2) { tv=a2; ti=b2; a2=a3; b2=b3; a3=tv; b3=ti;
          if (a2 > a1) { tv=a1; ti=b1; a1=a2; b1=b2; a2=tv; b2=ti;
            if (a1 > a0) { tv=a0; ti=b0; a0=a1; b0=b1; a1=tv; b1=ti; } } } } }
}

/* ==== kernel 3: merge, exact rescore, softmax, proto, score_dd =========== */
__global__ void k_score_dd2(const float* __restrict__ h_drug,
                            const float* __restrict__ h_dis,
                            const float* __restrict__ W,
                            const int*   __restrict__ src_dd,
                            const int*   __restrict__ dst_dd,
                            const int*   __restrict__ deg,
                            float*       __restrict__ out) {
    int e    = (blockIdx.x * blockDim.x + threadIdx.x) >> 5;
    int lane = threadIdx.x & 31;
    if (e >= E_DD) return;
    int didx = dst_dd[e];

    int c0 = -1, c1 = -1, c2 = -1, c3 = -1, c4 = -1, c5 = -1;
    if (lane == 0) {
        float a0=-1e30f,a1=-1e30f,a2=-1e30f,a3=-1e30f,a4=-1e30f,a5=-1e30f;
        int   b0=-1,b1=-1,b2=-1,b3=-1,b4=-1,b5=-1;
        int cb = e * NSPLIT * 4;
        #pragma unroll 4
        for (int s = 0; s < NSPLIT * 4; s++) {
            int id = g_ci[cb + s];
            if (id >= 0) ins6(g_cv[cb + s], id, a0,b0,a1,b1,a2,b2,a3,b3,a4,b4,a5,b5);
        }
        c0=b0; c1=b1; c2=b2; c3=b3; c4=b4; c5=b5;
    }
    c0 = __shfl_sync(0xffffffffu, c0, 0);
    c1 = __shfl_sync(0xffffffffu, c1, 0);
    c2 = __shfl_sync(0xffffffffu, c2, 0);
    c3 = __shfl_sync(0xffffffffu, c3, 0);
    c4 = __shfl_sync(0xffffffffu, c4, 0);
    c5 = __shfl_sync(0xffffffffu, c5, 0);

    /* exact fp32 rescore of 6 candidates (normalized rows, as reference) */
    float4 qa = ((const float4*)g_nd)[didx * 32 + lane];
    float val[6]; int cid[6] = {c0, c1, c2, c3, c4, c5};
    #pragma unroll
    for (int c = 0; c < 6; c++) {
        float r = -1e30f;
        if (cid[c] >= 0) {
            float4 bb = ((const float4*)g_nd)[cid[c] * 32 + lane];
            r = qa.x*bb.x + qa.y*bb.y + qa.z*bb.z + qa.w*bb.w;
            #pragma unroll
            for (int o = 16; o; o >>= 1) r += __shfl_xor_sync(0xffffffffu, r, o);
        }
        val[c] = r;
    }

    float w0 = 0.f, w1 = 0.f, w2 = 0.f;
    int   i0 = 0, i1 = 0, i2 = 0;
    if (lane == 0) {
        float v0 = -1e30f, v1 = -1e30f, v2 = -1e30f;
        int   a0 = -1, a1 = -1, a2 = -1;
        #pragma unroll
        for (int c = 0; c < 6; c++)
            if (cid[c] >= 0) ins3(val[c], cid[c], v0, a0, v1, a1, v2, a2);
        float x1 = expf(v1 - v0), x2 = expf(v2 - v0);
        float s  = 1.f + x1 + x2;
        w0 = 1.f / s; w1 = x1 / s; w2 = x2 / s;
        i0 = a0; i1 = a1; i2 = a2;
    }
    w0 = __shfl_sync(0xffffffffu, w0, 0);
    w1 = __shfl_sync(0xffffffffu, w1, 0);
    w2 = __shfl_sync(0xffffffffu, w2, 0);
    i0 = __shfl_sync(0xffffffffu, i0, 0);
    i1 = __shfl_sync(0xffffffffu, i1, 0);
    i2 = __shfl_sync(0xffffffffu, i2, 0);

    int   sidx = src_dd[e];
    float coef = expf(-0.7f * (float)deg[didx]);
    float om   = 1.f - coef;

    float4 sv = ((const float4*)h_drug)[sidx * 32 + lane];
    float4 wv = ((const float4*)W)[lane];            /* W row 0 */
    float4 dv = ((const float4*)h_dis)[didx * 32 + lane];
    float4 p0 = ((const float4*)h_dis)[i0 * 32 + lane];
    float4 p1 = ((const float4*)h_dis)[i1 * 32 + lane];
    float4 p2 = ((const float4*)h_dis)[i2 * 32 + lane];

    float r =
        sv.x * wv.x * (om * dv.x + coef * (w0*p0.x + w1*p1.x + w2*p2.x)) +
        sv.y * wv.y * (om * dv.y + coef * (w0*p0.y + w1*p1.y + w2*p2.y)) +
        sv.z * wv.z * (om * dv.z + coef * (w0*p0.z + w1*p1.z + w2*p2.z)) +
        sv.w * wv.w * (om * dv.w + coef * (w0*p0.w + w1*p1.w + w2*p2.w));
    #pragma unroll
    for (int o = 16; o; o >>= 1) r += __shfl_xor_sync(0xffffffffu, r, o);
    if (lane == 0) out[e] = r;
}

/* ==== kernel 4: score_nn — warp per edge, L2-resident gather-dot ========= */
__global__ void k_score_nn(const float* __restrict__ h_dis,
                           const float* __restrict__ W,
                           const int*   __restrict__ src,
                           const int*   __restrict__ dst,
                           float*       __restrict__ out) {
    int e    = (int)((blockIdx.x * (unsigned)blockDim.x + threadIdx.x) >> 5);
    int lane = threadIdx.x & 31;
    if (e >= E_NN) return;
    int s = __ldg(src + e), d = __ldg(dst + e);
    float4 a = ((const float4*)h_dis)[s * 32 + lane];
    float4 b = ((const float4*)h_dis)[d * 32 + lane];
    float4 w = ((const float4*)W)[32 + lane];        /* W row 1 */
    float r = a.x*w.x*b.x + a.y*w.y*b.y + a.z*w.z*b.z + a.w*w.w*b.w;
    #pragma unroll
    for (int o = 16; o; o >>= 1) r += __shfl_xor_sync(0xffffffffu, r, o);
    if (lane == 0) out[E_DD + e] = r;
}

/* ========================================================================= */
extern "C" void kernel_launch(void* const* d_in, const int* in_sizes, int n_in,
                              void* d_out, int out_size) {
    const float* h_drug = (const float*)d_in[0];
    const float* h_dis  = (const float*)d_in[1];
    const float* W      = (const float*)d_in[2];
    const int*   src_dd = (const int*)d_in[3];
    const int*   dst_dd = (const int*)d_in[4];
    const int*   src_nn = (const int*)d_in[5];
    const int*   dst_nn = (const int*)d_in[6];
    const int*   deg    = (const int*)d_in[7];
    float* out = (float*)d_out;

    (void)cudaFuncSetAttribute(k_simtopk,
                               cudaFuncAttributeMaxDynamicSharedMemorySize,
                               SMEM_TOT);

    /* big memory-bound kernel first */
    k_score_nn<<<(E_NN * 32 + 255) / 256, 256>>>(h_dis, W, src_nn, dst_nn, out);

    k_inv_norm<<<(N_DIS * 32 + 255) / 256, 256>>>(h_dis);
    k_prep<<<(N_DIS * 16) / 256, 256>>>(h_dis);
    k_pack_q<<<(E_DD * 16) / 256, 256>>>(dst_dd);
    k_simtopk<<<dim3(16, NSPLIT), 256, SMEM_TOT>>>(dst_dd);
    k_score_dd2<<<(E_DD * 32 + 255) / 256, 256>>>(h_drug, h_dis, W,
                                                  src_dd, dst_dd, deg, out);
}